// round 9
// baseline (speedup 1.0000x reference)
#include <cuda_runtime.h>
#include <cuda_bf16.h>
#include <cstdint>

#define NROWS 8192
#define DDIM  1024
#define KCLS  80
#define C81   81
#define MSEL  2048
#define TOPK  100
#define NFLAT (NROWS*KCLS)
#define SCORE_T 0.05f
#define SCALE_CLAMP 4.135166556742356f
#define IMG_W 1216.0f
#define IMG_H 800.0f
#define MAX_COORD 1217.0f
#define EQ_CAP 2048
#define NB_CAP 2048
#define B_LO 15692          // bits(0.05f)>>16
#define B_N  565            // buckets up to bits(1.0f)>>16 inclusive
#define GEMM_BLOCKS 128
#define TRANS_BLOCKS 80

// ---------------- scratch (static __device__: no allocations) ----------------
__device__ float              g_probs[NFLAT];
__device__ unsigned long long g_cand[NFLAT];
__device__ int                g_hist1[B_N];
__device__ unsigned long long g_sel[MSEL];
__device__ float4             g_bwT[KCLS*DDIM];       // [cls][k] -> 4 deltas
__device__ float              g_boxes[MSEL*4];
__device__ float              g_obox[MSEL*4];
__device__ float              g_score[MSEL];
__device__ int                g_cls[MSEL];
__device__ unsigned char      g_valid[MSEL];
__device__ int d_nCand;

// ---------------- helpers ----------------
__device__ __forceinline__ float wmaxf(float v){
    #pragma unroll
    for (int o=16;o;o>>=1) v = fmaxf(v, __shfl_xor_sync(0xffffffffu, v, o));
    return v;
}
__device__ __forceinline__ float wsumf(float v){
    #pragma unroll
    for (int o=16;o;o>>=1) v += __shfl_xor_sync(0xffffffffu, v, o);
    return v;
}
__device__ __forceinline__ float lo32(unsigned long long v){ return __uint_as_float((unsigned)v); }
__device__ __forceinline__ float hi32(unsigned long long v){ return __uint_as_float((unsigned)(v>>32)); }

__device__ __forceinline__ void append_cand(bool pred, float p, int idx){
    unsigned bal = __ballot_sync(0xffffffffu, pred);
    if (!bal) return;
    int lane = threadIdx.x & 31;
    int leader = __ffs(bal) - 1;
    int base = 0;
    if (lane == leader) base = atomicAdd(&d_nCand, __popc(bal));
    base = __shfl_sync(0xffffffffu, base, leader);
    if (pred){
        unsigned u = __float_as_uint(p);
        atomicAdd(&g_hist1[(int)(u>>16) - B_LO], 1);
        int pos = base + __popc(bal & ((1u<<lane)-1u));
        g_cand[pos] = ((unsigned long long)u << 32) | (unsigned)idx;
    }
}

// ---------------- K1: cls GEMM + softmax + append; extra blocks transpose bbox_w ----------------
__global__ __launch_bounds__(256) void k_gemm_softmax(
    const float* __restrict__ x, const float* __restrict__ w, const float* __restrict__ b,
    const float* __restrict__ bw)
{
    const int tid = threadIdx.x;

    if (blockIdx.x >= GEMM_BLOCKS){
        const float4* bw4 = (const float4*)bw;
        int i0 = (blockIdx.x - GEMM_BLOCKS)*256 + tid;
        const int nT = TRANS_BLOCKS*256;
        for (int m = i0; m < KCLS*DDIM; m += nT){
            int cls = m >> 10;
            int k   = m & 1023;
            g_bwT[m] = bw4[k*KCLS + cls];
        }
        return;
    }

    __shared__ __align__(16) float xsT[32][66];
    __shared__ float ws[32][81];
    const int ty = tid >> 5, tx = tid & 31;
    const int row0 = blockIdx.x * 64;
    const bool has2 = (tx < 17);

    unsigned long long acc[4][3] = {};
    float rx[8]; float rw[11];
    {
        const float* xp = x + (size_t)row0 * DDIM;
        #pragma unroll
        for (int i=0;i<8;i++){ int e=tid+i*256; int r=e>>5, k=e&31; rx[i]=xp[(size_t)r*DDIM+k]; }
        #pragma unroll
        for (int i=0;i<11;i++){ int e=tid+i*256; if (e<32*81){ int k=e/81, c=e-k*81; rw[i]=w[(size_t)k*C81+c]; } }
    }

    for (int kc=0; kc<DDIM; kc+=32){
        #pragma unroll
        for (int i=0;i<8;i++){ int e=tid+i*256; int r=e>>5, k=e&31; xsT[k][r]=rx[i]; }
        #pragma unroll
        for (int i=0;i<11;i++){ int e=tid+i*256; if (e<32*81){ int k=e/81, c=e-k*81; ws[k][c]=rw[i]; } }
        __syncthreads();
        if (kc + 32 < DDIM){
            const float* xp = x + (size_t)row0*DDIM + kc + 32;
            const float* wp = w + (size_t)(kc+32)*C81;
            #pragma unroll
            for (int i=0;i<8;i++){ int e=tid+i*256; int r=e>>5, k=e&31; rx[i]=xp[(size_t)r*DDIM+k]; }
            #pragma unroll
            for (int i=0;i<11;i++){ int e=tid+i*256; if (e<32*81){ int k=e/81, c=e-k*81; rw[i]=wp[(size_t)k*C81+c]; } }
        }
        #pragma unroll
        for (int k=0;k<32;k++){
            float b0 = ws[k][tx];
            float b1 = ws[k][tx+32];
            float b2 = has2 ? ws[k][tx+64] : 0.f;
            unsigned long long b0d, b1d, b2d;
            asm("mov.b64 %0,{%1,%1};" : "=l"(b0d) : "f"(b0));
            asm("mov.b64 %0,{%1,%1};" : "=l"(b1d) : "f"(b1));
            asm("mov.b64 %0,{%1,%1};" : "=l"(b2d) : "f"(b2));
            #pragma unroll
            for (int p=0;p<4;p++){
                unsigned long long a = *(const unsigned long long*)&xsT[k][ty*8 + 2*p];
                asm("fma.rn.f32x2 %0,%1,%2,%0;" : "+l"(acc[p][0]) : "l"(a), "l"(b0d));
                asm("fma.rn.f32x2 %0,%1,%2,%0;" : "+l"(acc[p][1]) : "l"(a), "l"(b1d));
                asm("fma.rn.f32x2 %0,%1,%2,%0;" : "+l"(acc[p][2]) : "l"(a), "l"(b2d));
            }
        }
        __syncthreads();
    }

    const float bb0 = b[tx], bb1 = b[tx+32];
    const float bb2 = has2 ? b[tx+64] : 0.f;

    #pragma unroll
    for (int p=0;p<4;p++){
        #pragma unroll
        for (int h=0;h<2;h++){
            float l0 = (h ? hi32(acc[p][0]) : lo32(acc[p][0])) + bb0;
            float l1 = (h ? hi32(acc[p][1]) : lo32(acc[p][1])) + bb1;
            float l2 = has2 ? ((h ? hi32(acc[p][2]) : lo32(acc[p][2])) + bb2) : -3.4e38f;
            float m  = wmaxf(fmaxf(l0, fmaxf(l1, l2)));
            float e0 = expf(l0 - m), e1 = expf(l1 - m);
            float e2 = has2 ? expf(l2 - m) : 0.f;
            float s  = wsumf(e0 + e1 + e2);
            int row  = row0 + ty*8 + 2*p + h;
            float p0 = e0 / s, p1 = e1 / s;
            {
                int idx = row*KCLS + tx;
                g_probs[idx] = p0;
                append_cand(p0 > SCORE_T, p0, idx);
            }
            {
                int idx = row*KCLS + tx + 32;
                g_probs[idx] = p1;
                append_cand(p1 > SCORE_T, p1, idx);
            }
            {
                float p2 = (tx < 16) ? (e2 / s) : 0.f;
                int idx = row*KCLS + tx + 64;
                if (tx < 16) g_probs[idx] = p2;
                append_cand((tx < 16) && (p2 > SCORE_T), p2, idx);
            }
        }
    }
}

// ---------------- K2: fused selection (single-scan bucketing) ----------------
__global__ __launch_bounds__(1024) void k_select(){
    __shared__ unsigned long long sel[MSEL];        // 16KB
    __shared__ unsigned se[EQ_CAP];                 // 8KB
    __shared__ unsigned short bufLo[NB_CAP];        // 4KB
    __shared__ unsigned bufIdx[NB_CAP];             // 8KB
    __shared__ int hist[256];
    __shared__ int hA[B_N];
    __shared__ int s_nSel, s_nEq, s_nB;
    __shared__ unsigned s_cut;
    __shared__ int s_r, s_B, s_nab, s_sub;
    const int t = threadIdx.x;
    const int n = d_nCand;

    for (int i=t; i<B_N; i+=1024) hA[i] = g_hist1[i];
    for (int i=t; i<256; i+=1024) hist[i] = 0;
    if (t==0){ s_nSel=0; s_nEq=0; s_nB=0; }
    __syncthreads();
    if (t==0){
        int cum=0, B=-1, nab=0;
        for (int bi=B_N-1; bi>=0; bi--){
            int c = hA[bi];
            if (cum + c >= MSEL){ B = bi; nab = cum; break; }
            cum += c;
        }
        s_B = B; s_nab = (B>=0) ? nab : cum;
        if (B < 0){ s_cut = __float_as_uint(SCORE_T); s_r = 0; }
    }
    __syncthreads();
    const int B = s_B;

    if (B >= 0){
        const unsigned Bfull = (unsigned)(B + B_LO);
        // pass 1 (single scan): above-bucket -> sel, in-bucket -> buffer + hist[15:8]
        for (int i=t; i<n; i+=1024){
            unsigned long long key = g_cand[i];
            unsigned u = (unsigned)(key >> 32);
            unsigned bh = u >> 16;
            if (bh > Bfull){
                int p = atomicAdd(&s_nSel, 1);
                sel[p] = ((unsigned long long)(~(u | 0x80000000u)) << 32) | (unsigned)key;
            } else if (bh == Bfull){
                int p = atomicAdd(&s_nB, 1);
                if (p < NB_CAP){ bufLo[p] = (unsigned short)(u & 0xFFFFu); bufIdx[p] = (unsigned)key; }
                atomicAdd(&hist[(u >> 8) & 255u], 1);
            }
        }
        __syncthreads();
        if (t==0){
            int cum = s_nab, b1 = 0;
            for (int q=255; q>=0; q--){ int c=hist[q]; if (cum + c >= MSEL){ b1=q; break; } cum += c; }
            s_sub = b1; s_nab = cum;
        }
        __syncthreads();
        const int nB = s_nB;
        const unsigned b1 = (unsigned)s_sub;
        for (int i=t; i<256; i+=1024) hist[i] = 0;
        __syncthreads();
        if (nB <= NB_CAP){
            for (int i=t; i<nB; i+=1024){
                unsigned lo = bufLo[i];
                if ((lo >> 8) == b1) atomicAdd(&hist[lo & 255u], 1);
            }
        } else {
            const unsigned pfx = (Bfull << 8) | b1;
            for (int i=t; i<n; i+=1024){
                unsigned u = (unsigned)(g_cand[i] >> 32);
                if ((u >> 8) == pfx) atomicAdd(&hist[u & 255u], 1);
            }
        }
        __syncthreads();
        if (t==0){
            int cum = s_nab, b0 = 0;
            for (int q=255; q>=0; q--){ int c=hist[q]; if (cum + c >= MSEL){ b0=q; break; } cum += c; }
            s_cut = (Bfull << 16) | (b1 << 8) | (unsigned)b0;
            s_r = MSEL - cum;
        }
        __syncthreads();
        const unsigned cut = s_cut;
        if (nB <= NB_CAP){
            const unsigned cutLo = cut & 0xFFFFu;
            for (int i=t; i<nB; i+=1024){
                unsigned lo = bufLo[i];
                if (lo > cutLo){
                    int p = atomicAdd(&s_nSel, 1);
                    unsigned u = (Bfull << 16) | lo;
                    sel[p] = ((unsigned long long)(~(u | 0x80000000u)) << 32) | bufIdx[i];
                } else if (lo == cutLo){
                    int p = atomicAdd(&s_nEq, 1);
                    if (p < EQ_CAP) se[p] = bufIdx[i];
                }
            }
        } else {
            for (int i=t; i<n; i+=1024){
                unsigned long long key = g_cand[i];
                unsigned u = (unsigned)(key >> 32);
                if ((u >> 16) == Bfull){
                    if (u > cut){
                        int p = atomicAdd(&s_nSel, 1);
                        sel[p] = ((unsigned long long)(~(u | 0x80000000u)) << 32) | (unsigned)key;
                    } else if (u == cut){
                        int p = atomicAdd(&s_nEq, 1);
                        if (p < EQ_CAP) se[p] = (unsigned)key;
                    }
                }
            }
        }
        __syncthreads();
    } else {
        // fewer than MSEL above threshold: everything goes in
        for (int i=t; i<n; i+=1024){
            unsigned long long key = g_cand[i];
            unsigned u = (unsigned)(key >> 32);
            int p = atomicAdd(&s_nSel, 1);
            sel[p] = ((unsigned long long)(~(u | 0x80000000u)) << 32) | (unsigned)key;
        }
        __syncthreads();
    }

    // tie-break at cutoff: sort eq indices asc, take first r
    int r = s_r;
    if (r > 0){
        int ne = min(s_nEq, EQ_CAP);
        int np = 1; while (np < ne) np <<= 1;
        for (int i=t; i<np; i+=1024) if (i >= ne) se[i] = 0xFFFFFFFFu;
        __syncthreads();
        for (int k=2;k<=np;k<<=1)
            for (int j=k>>1;j>0;j>>=1){
                for (int base=0; base<np; base+=1024){
                    int i = base+t;
                    if (i < np){
                        int l = i^j;
                        if (l > i && l < np){
                            unsigned a = se[i], bb = se[l];
                            bool asc = (i & k) == 0;
                            if ((a > bb) == asc){ se[i]=bb; se[l]=a; }
                        }
                    }
                }
                __syncthreads();
            }
        unsigned long long hi = (unsigned long long)(~(s_cut | 0x80000000u)) << 32;
        int base = s_nSel;
        for (int i=t; i<r; i+=1024) sel[base+i] = hi | se[i];
        __syncthreads();
        if (t==0) s_nSel += r;
        __syncthreads();
    }

    // shortfall fill (rare)
    if (s_nSel < MSEL){
        __shared__ int wtot[32];
        __shared__ int scnt;
        if (t==0) scnt = s_nSel;
        __syncthreads();
        int lane = t & 31, wd = t >> 5;
        for (int base=0; base<NFLAT; base+=1024){
            int i = base + t;
            bool f = (i < NFLAT) && !(g_probs[i] > SCORE_T);
            unsigned bal = __ballot_sync(0xffffffffu, f);
            if (lane==0) wtot[wd] = __popc(bal);
            __syncthreads();
            int off = scnt;
            for (int w2=0; w2<wd; w2++) off += wtot[w2];
            int slot = off + __popc(bal & ((1u<<lane)-1u));
            if (f && slot < MSEL)
                sel[slot] = ((unsigned long long)0xBF800000u << 32) | (unsigned)i;
            __syncthreads();
            if (t==0){ int tt=0; for (int w2=0;w2<32;w2++) tt+=wtot[w2]; scnt += tt; }
            __syncthreads();
            if (scnt >= MSEL) break;
        }
    }
    __syncthreads();

    // bitonic sort 2048 (score desc, idx asc)
    for (int k=2;k<=MSEL;k<<=1)
        for (int j=k>>1;j>0;j>>=1){
            #pragma unroll
            for (int base=0; base<MSEL; base+=1024){
                int i = base+t, l = i^j;
                if (l > i){
                    unsigned long long a = sel[i], bb = sel[l];
                    bool asc = (i & k) == 0;
                    if ((a > bb) == asc){ sel[i]=bb; sel[l]=a; }
                }
            }
            __syncthreads();
        }
    for (int i=t; i<MSEL; i+=1024) g_sel[i] = sel[i];

    // reset for next replay
    for (int i=t; i<B_N; i+=1024) g_hist1[i] = 0;
    if (t==0) d_nCand = 0;
}

// ---------------- K3: per-candidate bbox dot + decode + clip + offset ----------------
__global__ __launch_bounds__(128) void k_decode(
    const float* __restrict__ x, const float* __restrict__ bb, const float* __restrict__ prop)
{
    int rank = blockIdx.x;
    int t = threadIdx.x;
    unsigned long long key = g_sel[rank];
    unsigned idx = (unsigned)key;
    int row = (int)(idx / KCLS);
    int cls = (int)(idx - (unsigned)row*KCLS);
    const float* xr = x + (size_t)row*DDIM;
    const float4* wt = g_bwT + (size_t)cls*DDIM;
    float a0=0.f,a1=0.f,a2=0.f,a3=0.f;
    #pragma unroll
    for (int k=t; k<DDIM; k+=128){
        float xv = xr[k];
        float4 wv = wt[k];
        a0 = fmaf(xv, wv.x, a0);
        a1 = fmaf(xv, wv.y, a1);
        a2 = fmaf(xv, wv.z, a2);
        a3 = fmaf(xv, wv.w, a3);
    }
    #pragma unroll
    for (int o=16;o;o>>=1){
        a0 += __shfl_down_sync(0xffffffffu, a0, o);
        a1 += __shfl_down_sync(0xffffffffu, a1, o);
        a2 += __shfl_down_sync(0xffffffffu, a2, o);
        a3 += __shfl_down_sync(0xffffffffu, a3, o);
    }
    __shared__ float red[4][4];
    if ((t & 31) == 0){ int w=t>>5; red[w][0]=a0; red[w][1]=a1; red[w][2]=a2; red[w][3]=a3; }
    __syncthreads();
    if (t == 0){
        int c4 = cls*4;
        float d0 = bb[c4+0] + red[0][0]+red[1][0]+red[2][0]+red[3][0];
        float d1 = bb[c4+1] + red[0][1]+red[1][1]+red[2][1]+red[3][1];
        float d2 = bb[c4+2] + red[0][2]+red[1][2]+red[2][2]+red[3][2];
        float d3 = bb[c4+3] + red[0][3]+red[1][3]+red[2][3]+red[3][3];
        float px1 = prop[row*4+0], py1 = prop[row*4+1];
        float px2 = prop[row*4+2], py2 = prop[row*4+3];
        float w  = px2 - px1, h = py2 - py1;
        float cx = px1 + 0.5f*w, cy = py1 + 0.5f*h;
        float dx = d0 / 10.0f, dy = d1 / 10.0f;
        float dw = fminf(d2 / 5.0f, SCALE_CLAMP);
        float dh = fminf(d3 / 5.0f, SCALE_CLAMP);
        float pcx = dx*w + cx, pcy = dy*h + cy;
        float pw = expf(dw)*w, ph = expf(dh)*h;
        float x1 = pcx - 0.5f*pw, y1 = pcy - 0.5f*ph;
        float x2 = pcx + 0.5f*pw, y2 = pcy + 0.5f*ph;
        x1 = fminf(fmaxf(x1, 0.f), IMG_W);
        x2 = fminf(fmaxf(x2, 0.f), IMG_W);
        y1 = fminf(fmaxf(y1, 0.f), IMG_H);
        y2 = fminf(fmaxf(y2, 0.f), IMG_H);
        g_boxes[rank*4+0]=x1; g_boxes[rank*4+1]=y1;
        g_boxes[rank*4+2]=x2; g_boxes[rank*4+3]=y2;
        float off = (float)cls * MAX_COORD;
        g_obox[rank*4+0]=x1+off; g_obox[rank*4+1]=y1+off;
        g_obox[rank*4+2]=x2+off; g_obox[rank*4+3]=y2+off;
        g_cls[rank] = cls;
        float p = g_probs[idx];
        bool v = p > SCORE_T;
        g_score[rank] = v ? p : -1.0f;
        g_valid[rank] = v ? 1 : 0;
    }
}

// ---------------- K4: single-block NMS (warp per class) + top-100 output ----------------
__global__ __launch_bounds__(1024) void k_nms_out(float* out){
    __shared__ unsigned char  s_cv[MSEL];        // cls if valid else 0xFF
    __shared__ float4         s_box[MSEL];       // offset boxes by rank (32KB)
    __shared__ unsigned short s_rank[MSEL];      // ranks grouped by class
    __shared__ unsigned char  s_sup[MSEL];
    __shared__ int s_cnt[KCLS];
    __shared__ int s_off[KCLS];
    const int t = threadIdx.x;
    const int lane = t & 31, w = t >> 5;

    // phase 0: load state
    #pragma unroll
    for (int i=t; i<MSEL; i+=1024){
        unsigned char v = g_valid[i];
        int c = g_cls[i];
        s_cv[i] = v ? (unsigned char)c : (unsigned char)0xFF;
        s_box[i] = *(const float4*)&g_obox[i*4];
        s_sup[i] = 0;
    }
    __syncthreads();

    // phase 1: per-class counts (warp w handles classes w, w+32, w+64)
    const int c0 = w, c1 = w + 32, c2 = w + 64;
    {
        int n0=0, n1=0, n2=0;
        for (int base=0; base<MSEL; base+=32){
            int bch = s_cv[base+lane];
            n0 += __popc(__ballot_sync(0xffffffffu, bch==c0));
            n1 += __popc(__ballot_sync(0xffffffffu, bch==c1));
            n2 += __popc(__ballot_sync(0xffffffffu, bch==c2));
        }
        if (lane==0){
            s_cnt[c0] = n0; s_cnt[c1] = n1;
            if (c2 < KCLS) s_cnt[c2] = n2;
        }
    }
    __syncthreads();
    // phase 2: prefix offsets (serial, 80 adds)
    if (t==0){
        int acc=0;
        for (int c=0;c<KCLS;c++){ s_off[c]=acc; acc+=s_cnt[c]; }
    }
    __syncthreads();
    // phase 3: emit rank lists (rank order preserved)
    {
        int p0 = s_off[c0], p1 = s_off[c1], p2 = (c2 < KCLS) ? s_off[c2] : 0;
        for (int base=0; base<MSEL; base+=32){
            int bch = s_cv[base+lane];
            unsigned m0 = __ballot_sync(0xffffffffu, bch==c0);
            unsigned m1 = __ballot_sync(0xffffffffu, bch==c1);
            unsigned m2 = __ballot_sync(0xffffffffu, bch==c2);
            unsigned lt = (1u<<lane)-1u;
            if (bch==c0) s_rank[p0 + __popc(m0 & lt)] = (unsigned short)(base+lane);
            else if (bch==c1) s_rank[p1 + __popc(m1 & lt)] = (unsigned short)(base+lane);
            else if (bch==c2 && c2 < KCLS) s_rank[p2 + __popc(m2 & lt)] = (unsigned short)(base+lane);
            p0 += __popc(m0); p1 += __popc(m1); p2 += __popc(m2);
        }
    }
    __syncthreads();

    // phase 4: greedy NMS, one warp per class, no block barriers
    for (int cc=0; cc<3; cc++){
        int c = w + cc*32;
        if (c >= KCLS) break;
        const int off = s_off[c], n = s_cnt[c];
        if (n <= 1) continue;
        const int nq = (n + 31) >> 5;
        // cache per-lane boxes for j = lane + 32q, q<4 (n<=128 fast path)
        float4 bjc[4]; float ajc[4];
        #pragma unroll
        for (int q=0; q<4; q++){
            int j = lane + 32*q;
            if (j < n){
                bjc[q] = s_box[s_rank[off+j]];
                ajc[q] = (bjc[q].z-bjc[q].x)*(bjc[q].w-bjc[q].y);
            }
        }
        unsigned long long sup = 0;
        for (int k=0; k<n-1; k++){
            unsigned long long sk = __shfl_sync(0xffffffffu, sup, k & 31);
            if ((sk >> (k >> 5)) & 1ull) continue;
            float4 bk = s_box[s_rank[off+k]];           // broadcast LDS.128
            float ak = (bk.z-bk.x)*(bk.w-bk.y);
            #pragma unroll
            for (int q=0; q<4; q++){
                if (q >= nq) break;
                int j = lane + 32*q;
                if (j > k && j < n && !((sup>>q)&1ull)){
                    float xx1=fmaxf(bk.x,bjc[q].x), yy1=fmaxf(bk.y,bjc[q].y);
                    float xx2=fminf(bk.z,bjc[q].z), yy2=fminf(bk.w,bjc[q].w);
                    float inter=fmaxf(xx2-xx1,0.f)*fmaxf(yy2-yy1,0.f);
                    float un=fmaxf(ak+ajc[q]-inter,1e-9f);
                    if (inter/un > 0.5f) sup |= (1ull<<q);
                }
            }
            for (int q=4; q<nq; q++){
                int j = lane + 32*q;
                if (j > k && j < n && !((sup>>q)&1ull)){
                    float4 bb = s_box[s_rank[off+j]];
                    float ar = (bb.z-bb.x)*(bb.w-bb.y);
                    float xx1=fmaxf(bk.x,bb.x), yy1=fmaxf(bk.y,bb.y);
                    float xx2=fminf(bk.z,bb.z), yy2=fminf(bk.w,bb.w);
                    float inter=fmaxf(xx2-xx1,0.f)*fmaxf(yy2-yy1,0.f);
                    float un=fmaxf(ak+ar-inter,1e-9f);
                    if (inter/un > 0.5f) sup |= (1ull<<q);
                }
            }
        }
        for (int q=0; q<nq; q++){
            int j = lane + 32*q;
            if (j < n && ((sup>>q)&1ull)) s_sup[s_rank[off+j]] = 1;
        }
    }
    __syncthreads();

    // phase 5: keep-scan + emit top-100 (1024 threads x 2 entries)
    {
        __shared__ int warpS[32];
        __shared__ int s_tot;
        int i0 = 2*t, i1 = 2*t+1;
        int k0 = (s_cv[i0] != 0xFF && !s_sup[i0]) ? 1 : 0;
        int k1 = (s_cv[i1] != 0xFF && !s_sup[i1]) ? 1 : 0;
        int ps = k0 + k1;
        int v = ps;
        #pragma unroll
        for (int o=1;o<32;o<<=1){ int nn = __shfl_up_sync(0xffffffffu, v, o); if (lane>=o) v += nn; }
        if (lane==31) warpS[w] = v;
        __syncthreads();
        if (t==0){
            int acc=0;
            #pragma unroll
            for (int w2=0;w2<32;w2++){ int tmp=warpS[w2]; warpS[w2]=acc; acc+=tmp; }
            s_tot = acc;
        }
        __syncthreads();
        int ex0 = (v - ps) + warpS[w];
        const int nK = s_tot;
        {
            int slot = k0 ? ex0 : (nK + (i0 - ex0));
            if (slot < TOPK){
                out[slot*4+0] = g_boxes[i0*4+0];
                out[slot*4+1] = g_boxes[i0*4+1];
                out[slot*4+2] = g_boxes[i0*4+2];
                out[slot*4+3] = g_boxes[i0*4+3];
                out[400+slot] = k0 ? g_score[i0] : -1.0f;
                out[500+slot] = (float)g_cls[i0];
                out[600+slot] = k0 ? 1.0f : 0.0f;
            }
        }
        {
            int pk = ex0 + k0;
            int slot = k1 ? pk : (nK + (i1 - pk));
            if (slot < TOPK){
                out[slot*4+0] = g_boxes[i1*4+0];
                out[slot*4+1] = g_boxes[i1*4+1];
                out[slot*4+2] = g_boxes[i1*4+2];
                out[slot*4+3] = g_boxes[i1*4+3];
                out[400+slot] = k1 ? g_score[i1] : -1.0f;
                out[500+slot] = (float)g_cls[i1];
                out[600+slot] = k1 ? 1.0f : 0.0f;
            }
        }
    }
}

// ---------------- launch ----------------
extern "C" void kernel_launch(void* const* d_in, const int* in_sizes, int n_in,
                              void* d_out, int out_size){
    const float* x    = (const float*)d_in[0];
    const float* clsw = (const float*)d_in[1];
    const float* clsb = (const float*)d_in[2];
    const float* bw   = (const float*)d_in[3];
    const float* bbias= (const float*)d_in[4];
    const float* prop = (const float*)d_in[5];
    float* out = (float*)d_out;

    k_gemm_softmax<<<GEMM_BLOCKS + TRANS_BLOCKS, 256>>>(x, clsw, clsb, bw);
    k_select<<<1, 1024>>>();
    k_decode<<<MSEL, 128>>>(x, bbias, prop);
    k_nms_out<<<1, 1024>>>(out);
}